// round 3
// baseline (speedup 1.0000x reference)
#include <cuda_runtime.h>
#include <cooperative_groups.h>
#include <math.h>

namespace cg = cooperative_groups;

// Fixed problem shape (ReRanker reference): B=256, C=128, D=1024, fp32.
#define BB 256
#define CC 128
#define DD 1024
#define CSZ 4              // cluster size: 4 CTAs per batch
#define RPC 32             // rows per CTA (CC / CSZ)
#define NW 8               // 256 threads, 8 warps per CTA
#define EPS 1e-8f

struct Smem {
    float4 rows[RPC][DD / 4];   // 128 KB — candidate rows, SMEM-resident
    float4 docs[DD / 4];        // 4 KB
    float4 sums[DD / 4];        // 4 KB
    float4 swp[NW][DD / 4];     // 32 KB — warp-private partial S
    float4 Spart[DD / 4];       // 4 KB  — CTA-partial S (peer-readable)
    float  rcn_s[RPC];
    float  red[3][NW];
    float  wsum[NW];
    float  cta_scpart;          // peer-readable partial of summary_avg
    float  sc_rdn, sc_rsn;
};

extern "C" __global__ void __launch_bounds__(256, 1) __cluster_dims__(CSZ, 1, 1)
reranker_cluster_kernel(
    const float* __restrict__ doc,
    const float* __restrict__ summ,
    const float* __restrict__ cand,
    float* __restrict__ out)
{
    extern __shared__ char smem_raw[];
    Smem* s = reinterpret_cast<Smem*>(smem_raw);

    cg::cluster_group cluster = cg::this_cluster();

    const int b    = blockIdx.x >> 2;
    const int rank = blockIdx.x & 3;
    const int row0 = rank * RPC;
    const int tid  = threadIdx.x;
    const int w    = tid >> 5;
    const int l    = tid & 31;

    // ---- load doc/summary rows, compute dn, sn, doc·summary ----
    {
        const float4* docg = (const float4*)(doc  + (size_t)b * DD);
        const float4* sumg = (const float4*)(summ + (size_t)b * DD);
        float4 dv = docg[tid];
        float4 sv = sumg[tid];
        s->docs[tid] = dv;
        s->sums[tid] = sv;

        float pdd = dv.x*dv.x + dv.y*dv.y + dv.z*dv.z + dv.w*dv.w;
        float pss = sv.x*sv.x + sv.y*sv.y + sv.z*sv.z + sv.w*sv.w;
        float pds = dv.x*sv.x + dv.y*sv.y + dv.z*sv.z + dv.w*sv.w;
        #pragma unroll
        for (int o = 16; o; o >>= 1) {
            pdd += __shfl_xor_sync(0xffffffffu, pdd, o);
            pss += __shfl_xor_sync(0xffffffffu, pss, o);
            pds += __shfl_xor_sync(0xffffffffu, pds, o);
        }
        if (l == 0) { s->red[0][w] = pdd; s->red[1][w] = pss; s->red[2][w] = pds; }
    }
    __syncthreads();
    if (tid == 0) {
        float dd = 0.f, ss = 0.f, ds = 0.f;
        #pragma unroll
        for (int i = 0; i < NW; i++) { dd += s->red[0][i]; ss += s->red[1][i]; ds += s->red[2][i]; }
        float dn = fmaxf(sqrtf(dd), EPS);
        float sn = fmaxf(sqrtf(ss), EPS);
        s->sc_rdn = 1.0f / dn;
        s->sc_rsn = 1.0f / sn;
        if (rank == 0)
            out[2 * BB * CC + b] = ds / (dn * sn);      // summary_score[b]
    }
    __syncthreads();
    const float rdn = s->sc_rdn;
    const float rsn = s->sc_rsn;

    // ---- Pass A: stream 32 rows into SMEM; norms, outer, summary·cand, partial S ----
    const float4* cb = (const float4*)(cand + ((size_t)b * CC + row0) * DD);
    float4 Sacc[8];
    #pragma unroll
    for (int i = 0; i < 8; i++) Sacc[i] = make_float4(0.f, 0.f, 0.f, 0.f);
    float scpart = 0.f;

    #pragma unroll
    for (int j = 0; j < RPC / NW; j++) {
        const int rl = w * (RPC / NW) + j;              // local row 0..31
        const float4* rowp = cb + (size_t)rl * (DD / 4);
        float4 v[8];
        #pragma unroll
        for (int i = 0; i < 8; i++) v[i] = rowp[i * 32 + l];
        #pragma unroll
        for (int i = 0; i < 8; i++) s->rows[rl][i * 32 + l] = v[i];

        float ss = 0.f, dd = 0.f, sd = 0.f;
        #pragma unroll
        for (int i = 0; i < 8; i++) {
            float4 a  = v[i];
            float4 d4 = s->docs[i * 32 + l];
            float4 s4 = s->sums[i * 32 + l];
            ss = fmaf(a.x, a.x, ss); ss = fmaf(a.y, a.y, ss);
            ss = fmaf(a.z, a.z, ss); ss = fmaf(a.w, a.w, ss);
            dd = fmaf(a.x, d4.x, dd); dd = fmaf(a.y, d4.y, dd);
            dd = fmaf(a.z, d4.z, dd); dd = fmaf(a.w, d4.w, dd);
            sd = fmaf(a.x, s4.x, sd); sd = fmaf(a.y, s4.y, sd);
            sd = fmaf(a.z, s4.z, sd); sd = fmaf(a.w, s4.w, sd);
        }
        #pragma unroll
        for (int o = 16; o; o >>= 1) {
            ss += __shfl_xor_sync(0xffffffffu, ss, o);
            dd += __shfl_xor_sync(0xffffffffu, dd, o);
            sd += __shfl_xor_sync(0xffffffffu, sd, o);
        }
        float cn  = fmaxf(sqrtf(ss), EPS);
        float rcn = 1.0f / cn;
        if (l == 0) {
            out[b * CC + row0 + rl] = dd * rcn * rdn;   // outer_score
            s->rcn_s[rl] = rcn;
        }
        scpart = fmaf(sd, rcn, scpart);
        #pragma unroll
        for (int i = 0; i < 8; i++) {
            Sacc[i].x = fmaf(v[i].x, rcn, Sacc[i].x);
            Sacc[i].y = fmaf(v[i].y, rcn, Sacc[i].y);
            Sacc[i].z = fmaf(v[i].z, rcn, Sacc[i].z);
            Sacc[i].w = fmaf(v[i].w, rcn, Sacc[i].w);
        }
    }

    // ---- fold warp-private S copies -> Spart (CTA partial), wsum -> cta_scpart ----
    #pragma unroll
    for (int i = 0; i < 8; i++) s->swp[w][i * 32 + l] = Sacc[i];
    if (l == 0) s->wsum[w] = scpart;
    __syncthreads();
    {
        float4 st = s->swp[0][tid];
        #pragma unroll
        for (int ww = 1; ww < NW; ww++) {
            float4 t = s->swp[ww][tid];
            st.x += t.x; st.y += t.y; st.z += t.z; st.w += t.w;
        }
        s->Spart[tid] = st;
    }
    if (tid == 0) {
        float acc = 0.f;
        #pragma unroll
        for (int i = 0; i < NW; i++) acc += s->wsum[i];
        s->cta_scpart = acc;
    }
    __syncthreads();

    // ---- cluster-wide S reduction via DSMEM ----
    cluster.sync();

    float4 sreg[8];
    #pragma unroll
    for (int i = 0; i < 8; i++) sreg[i] = s->Spart[i * 32 + l];
    #pragma unroll
    for (int pr = 0; pr < CSZ; pr++) {
        if (pr == rank) continue;
        Smem* ps = (Smem*)cluster.map_shared_rank((void*)s, pr);
        #pragma unroll
        for (int i = 0; i < 8; i++) {
            float4 t = ps->Spart[i * 32 + l];
            sreg[i].x += t.x; sreg[i].y += t.y; sreg[i].z += t.z; sreg[i].w += t.w;
        }
    }

    if (rank == 0 && tid == 0) {
        float acc = s->cta_scpart;
        #pragma unroll
        for (int pr = 1; pr < CSZ; pr++) {
            Smem* ps = (Smem*)cluster.map_shared_rank((void*)s, pr);
            acc += ps->cta_scpart;
        }
        out[2 * BB * CC + BB + b] = acc * rsn * (1.0f / CC);   // summary_avg_score[b]
    }

    // all DSMEM reads done before any CTA may proceed to exit
    cluster.sync();

    // ---- Pass B: inner score from SMEM-resident rows ----
    #pragma unroll
    for (int j = 0; j < RPC / NW; j++) {
        const int rl = w * (RPC / NW) + j;
        float dot = 0.f;
        #pragma unroll
        for (int i = 0; i < 8; i++) {
            float4 a = s->rows[rl][i * 32 + l];
            float4 t = sreg[i];
            dot = fmaf(a.x, t.x, dot); dot = fmaf(a.y, t.y, dot);
            dot = fmaf(a.z, t.z, dot); dot = fmaf(a.w, t.w, dot);
        }
        #pragma unroll
        for (int o = 16; o; o >>= 1)
            dot += __shfl_xor_sync(0xffffffffu, dot, o);
        if (l == 0) {
            // chat_r · S includes the self term (==1 up to fp32 rounding)
            out[BB * CC + b * CC + row0 + rl] =
                (dot * s->rcn_s[rl] - 1.0f) * (1.0f / (CC - 1));
        }
    }
}

extern "C" void kernel_launch(void* const* d_in, const int* in_sizes, int n_in,
                              void* d_out, int out_size) {
    const float* doc  = (const float*)d_in[0];   // [B, D]
    const float* summ = (const float*)d_in[1];   // [B, D]
    const float* cand = (const float*)d_in[2];   // [B, C, D]
    float* out = (float*)d_out;                  // [B*C | B*C | B | B]
    (void)in_sizes; (void)n_in; (void)out_size;

    cudaFuncSetAttribute(reranker_cluster_kernel,
                         cudaFuncAttributeMaxDynamicSharedMemorySize,
                         (int)sizeof(Smem));

    reranker_cluster_kernel<<<BB * CSZ, 256, sizeof(Smem)>>>(doc, summ, cand, out);
}

// round 4
// speedup vs baseline: 1.5568x; 1.5568x over previous
#include <cuda_runtime.h>
#include <math.h>

// Fixed problem shape (ReRanker reference): B=256, C=128, D=1024, fp32.
#define BB 256
#define CC 128
#define DD 1024
#define HALF_ROWS 64       // rows per CTA (2 CTAs per batch)
#define NW 8               // 256 threads, 8 warps
#define RPW 8              // rows per warp (HALF_ROWS / NW)
#define EPS 1e-8f

// Scratch (device globals — no allocation at runtime).
__device__ float  g_Spart[BB][2][DD];   // 2 MB: per-half partial S
__device__ float  g_rcn[BB][CC];        // 128 KB: 1/candidate-norm
__device__ float  g_scpart[BB][2];      // partial of sum_c (summ·cand_c)/cn_c
__device__ float  g_rsn[BB];            // 1/summary-norm

// ================= K1: stream cand once; norms, outer, summary dots, partial S ==========
__global__ __launch_bounds__(256, 2) void k1_stream(
    const float* __restrict__ doc,
    const float* __restrict__ summ,
    const float* __restrict__ cand,
    float* __restrict__ out)
{
    const int b    = blockIdx.x >> 1;
    const int half = blockIdx.x & 1;
    const int row0 = half * HALF_ROWS;
    const int tid  = threadIdx.x;
    const int w    = tid >> 5;
    const int l    = tid & 31;

    __shared__ float4 docs[DD / 4];          // 4 KB
    __shared__ float4 sums[DD / 4];          // 4 KB
    __shared__ float4 swp[NW][DD / 4];       // 32 KB warp-private partial S
    __shared__ float  red[3][NW];
    __shared__ float  wsum[NW];
    __shared__ float  sc_rdn, sc_rsn;

    // ---- doc/summary: norms + doc·summary ----
    {
        const float4* docg = (const float4*)(doc  + (size_t)b * DD);
        const float4* sumg = (const float4*)(summ + (size_t)b * DD);
        float4 dv = docg[tid];
        float4 sv = sumg[tid];
        docs[tid] = dv;
        sums[tid] = sv;
        float pdd = dv.x*dv.x + dv.y*dv.y + dv.z*dv.z + dv.w*dv.w;
        float pss = sv.x*sv.x + sv.y*sv.y + sv.z*sv.z + sv.w*sv.w;
        float pds = dv.x*sv.x + dv.y*sv.y + dv.z*sv.z + dv.w*sv.w;
        #pragma unroll
        for (int o = 16; o; o >>= 1) {
            pdd += __shfl_xor_sync(0xffffffffu, pdd, o);
            pss += __shfl_xor_sync(0xffffffffu, pss, o);
            pds += __shfl_xor_sync(0xffffffffu, pds, o);
        }
        if (l == 0) { red[0][w] = pdd; red[1][w] = pss; red[2][w] = pds; }
    }
    __syncthreads();
    if (tid == 0) {
        float dd = 0.f, ss = 0.f, ds = 0.f;
        #pragma unroll
        for (int i = 0; i < NW; i++) { dd += red[0][i]; ss += red[1][i]; ds += red[2][i]; }
        float dn = fmaxf(sqrtf(dd), EPS);
        float sn = fmaxf(sqrtf(ss), EPS);
        sc_rdn = 1.0f / dn;
        sc_rsn = 1.0f / sn;
        if (half == 0) {
            out[2 * BB * CC + b] = ds / (dn * sn);      // summary_score[b]
            g_rsn[b] = 1.0f / sn;
        }
    }
    __syncthreads();
    const float rdn = sc_rdn;

    // ---- stream 64 rows (software-pipelined: next row's loads issued before compute) ----
    const float4* cb = (const float4*)(cand + ((size_t)b * CC + row0) * DD);
    float4 Sacc[8];
    #pragma unroll
    for (int i = 0; i < 8; i++) Sacc[i] = make_float4(0.f, 0.f, 0.f, 0.f);
    float scpart = 0.f;

    float4 vc[8];
    {
        const float4* rowp = cb + (size_t)w * (DD / 4);   // row index: w + j*NW, j=0
        #pragma unroll
        for (int i = 0; i < 8; i++) vc[i] = rowp[i * 32 + l];
    }

    #pragma unroll
    for (int j = 0; j < RPW; j++) {
        const int rl = w + j * NW;
        float4 vn[8];
        if (j + 1 < RPW) {
            const float4* nrow = cb + (size_t)(rl + NW) * (DD / 4);
            #pragma unroll
            for (int i = 0; i < 8; i++) vn[i] = nrow[i * 32 + l];
        }

        float ss = 0.f, dd = 0.f, sd = 0.f;
        #pragma unroll
        for (int i = 0; i < 8; i++) {
            float4 a  = vc[i];
            float4 d4 = docs[i * 32 + l];
            float4 s4 = sums[i * 32 + l];
            ss = fmaf(a.x, a.x, ss); ss = fmaf(a.y, a.y, ss);
            ss = fmaf(a.z, a.z, ss); ss = fmaf(a.w, a.w, ss);
            dd = fmaf(a.x, d4.x, dd); dd = fmaf(a.y, d4.y, dd);
            dd = fmaf(a.z, d4.z, dd); dd = fmaf(a.w, d4.w, dd);
            sd = fmaf(a.x, s4.x, sd); sd = fmaf(a.y, s4.y, sd);
            sd = fmaf(a.z, s4.z, sd); sd = fmaf(a.w, s4.w, sd);
        }
        #pragma unroll
        for (int o = 16; o; o >>= 1) {
            ss += __shfl_xor_sync(0xffffffffu, ss, o);
            dd += __shfl_xor_sync(0xffffffffu, dd, o);
            sd += __shfl_xor_sync(0xffffffffu, sd, o);
        }
        float cn  = fmaxf(sqrtf(ss), EPS);
        float rcn = 1.0f / cn;
        if (l == 0) {
            const int r = row0 + rl;
            out[b * CC + r] = dd * rcn * rdn;           // outer_score[b,r]
            g_rcn[b][r] = rcn;
        }
        scpart = fmaf(sd, rcn, scpart);                  // same across lanes
        #pragma unroll
        for (int i = 0; i < 8; i++) {
            Sacc[i].x = fmaf(vc[i].x, rcn, Sacc[i].x);
            Sacc[i].y = fmaf(vc[i].y, rcn, Sacc[i].y);
            Sacc[i].z = fmaf(vc[i].z, rcn, Sacc[i].z);
            Sacc[i].w = fmaf(vc[i].w, rcn, Sacc[i].w);
        }
        #pragma unroll
        for (int i = 0; i < 8; i++) vc[i] = vn[i];
    }

    // ---- fold warp partials; write half-batch S + scpart scratch ----
    #pragma unroll
    for (int i = 0; i < 8; i++) swp[w][i * 32 + l] = Sacc[i];
    if (l == 0) wsum[w] = scpart;
    __syncthreads();
    {
        float4 st = swp[0][tid];
        #pragma unroll
        for (int ww = 1; ww < NW; ww++) {
            float4 t = swp[ww][tid];
            st.x += t.x; st.y += t.y; st.z += t.z; st.w += t.w;
        }
        ((float4*)g_Spart[b][half])[tid] = st;
    }
    if (tid == 0) {
        float acc = 0.f;
        #pragma unroll
        for (int i = 0; i < NW; i++) acc += wsum[i];
        g_scpart[b][half] = acc;
    }
}

// ================= K2: reverse-b stream; inner scores =====================
__global__ __launch_bounds__(256, 4) void k2_inner(
    const float* __restrict__ cand,
    float* __restrict__ out)
{
    const int b    = BB - 1 - (blockIdx.x >> 1);   // reversed: ride K1's L2 tail
    const int half = blockIdx.x & 1;
    const int row0 = half * HALF_ROWS;
    const int tid  = threadIdx.x;
    const int w    = tid >> 5;
    const int l    = tid & 31;

    __shared__ float4 Ssm[DD / 4];   // 4 KB

    {
        const float4* s0 = (const float4*)g_Spart[b][0];
        const float4* s1 = (const float4*)g_Spart[b][1];
        float4 a = s0[tid];
        float4 c = s1[tid];
        a.x += c.x; a.y += c.y; a.z += c.z; a.w += c.w;
        Ssm[tid] = a;
    }
    if (half == 0 && tid == 0) {
        out[2 * BB * CC + BB + b] =
            (g_scpart[b][0] + g_scpart[b][1]) * g_rsn[b] * (1.0f / CC);  // summary_avg
    }
    __syncthreads();

    const float4* cb = (const float4*)(cand + ((size_t)b * CC + row0) * DD);

    float4 vc[8];
    {
        const float4* rowp = cb + (size_t)w * (DD / 4);
        #pragma unroll
        for (int i = 0; i < 8; i++) vc[i] = rowp[i * 32 + l];
    }

    #pragma unroll
    for (int j = 0; j < RPW; j++) {
        const int rl = w + j * NW;
        float4 vn[8];
        if (j + 1 < RPW) {
            const float4* nrow = cb + (size_t)(rl + NW) * (DD / 4);
            #pragma unroll
            for (int i = 0; i < 8; i++) vn[i] = nrow[i * 32 + l];
        }

        float dot = 0.f;
        #pragma unroll
        for (int i = 0; i < 8; i++) {
            float4 a = vc[i];
            float4 s = Ssm[i * 32 + l];
            dot = fmaf(a.x, s.x, dot); dot = fmaf(a.y, s.y, dot);
            dot = fmaf(a.z, s.z, dot); dot = fmaf(a.w, s.w, dot);
        }
        #pragma unroll
        for (int o = 16; o; o >>= 1)
            dot += __shfl_xor_sync(0xffffffffu, dot, o);
        if (l == 0) {
            const int r = row0 + rl;
            // chat_r · S includes the self term (==1 up to fp32 rounding)
            out[BB * CC + b * CC + r] =
                (dot * g_rcn[b][r] - 1.0f) * (1.0f / (CC - 1));
        }
        #pragma unroll
        for (int i = 0; i < 8; i++) vc[i] = vn[i];
    }
}

extern "C" void kernel_launch(void* const* d_in, const int* in_sizes, int n_in,
                              void* d_out, int out_size) {
    const float* doc  = (const float*)d_in[0];   // [B, D]
    const float* summ = (const float*)d_in[1];   // [B, D]
    const float* cand = (const float*)d_in[2];   // [B, C, D]
    float* out = (float*)d_out;                  // [B*C | B*C | B | B]
    (void)in_sizes; (void)n_in; (void)out_size;

    k1_stream<<<BB * 2, 256>>>(doc, summ, cand, out);
    k2_inner <<<BB * 2, 256>>>(cand, out);
}

// round 6
// speedup vs baseline: 2.0689x; 1.3289x over previous
#include <cuda_runtime.h>
#include <math.h>

// Fixed problem shape (ReRanker reference): B=256, C=128, D=1024, fp32.
#define BB 256
#define CC 128
#define DD 1024
#define HALF_ROWS 64       // rows per CTA (2 CTAs per batch)
#define NW 8               // 256 threads, 8 warps
#define RPW 8              // rows per warp (HALF_ROWS / NW)
#define EPS 1e-8f
#define EPS2 1e-16f

// Scratch (device globals — no allocation at runtime).
__device__ float  g_Spart[BB][2][DD];   // 2 MB: per-half partial S
__device__ float  g_rcn[BB][CC];        // 128 KB: 1/candidate-norm
__device__ float  g_scpart[BB][2];      // partial of sum_c (summ·cand_c)/cn_c
__device__ float  g_rsn[BB];            // 1/summary-norm

struct F8 { float4 lo, hi; };

__device__ __forceinline__ F8 unpack(unsigned long long u0, unsigned long long u1,
                                     unsigned long long u2, unsigned long long u3) {
    F8 v;
    v.lo.x = __uint_as_float((unsigned)u0); v.lo.y = __uint_as_float((unsigned)(u0 >> 32));
    v.lo.z = __uint_as_float((unsigned)u1); v.lo.w = __uint_as_float((unsigned)(u1 >> 32));
    v.hi.x = __uint_as_float((unsigned)u2); v.hi.y = __uint_as_float((unsigned)(u2 >> 32));
    v.hi.z = __uint_as_float((unsigned)u3); v.hi.w = __uint_as_float((unsigned)(u3 >> 32));
    return v;
}

// 32-byte L2-eviction-priority loads (legal form on sm_103: .v4.b64).
__device__ __forceinline__ F8 ldg_evict_last(const float* p) {
    unsigned long long u0, u1, u2, u3;
    asm volatile("ld.global.nc.L2::evict_last.v4.b64 {%0,%1,%2,%3}, [%4];"
                 : "=l"(u0), "=l"(u1), "=l"(u2), "=l"(u3) : "l"(p));
    return unpack(u0, u1, u2, u3);
}
__device__ __forceinline__ F8 ldg_evict_first(const float* p) {
    unsigned long long u0, u1, u2, u3;
    asm volatile("ld.global.nc.L2::evict_first.v4.b64 {%0,%1,%2,%3}, [%4];"
                 : "=l"(u0), "=l"(u1), "=l"(u2), "=l"(u3) : "l"(p));
    return unpack(u0, u1, u2, u3);
}

// ====== K1: stream cand once (pin in L2); norms, outer, summary dots, partial S ======
__global__ __launch_bounds__(256, 2) void k1_stream(
    const float* __restrict__ doc,
    const float* __restrict__ summ,
    const float* __restrict__ cand,
    float* __restrict__ out)
{
    const int b    = blockIdx.x >> 1;
    const int half = blockIdx.x & 1;
    const int row0 = half * HALF_ROWS;
    const int tid  = threadIdx.x;
    const int w    = tid >> 5;
    const int l    = tid & 31;

    __shared__ float4 docs[DD / 4];          // 4 KB
    __shared__ float4 sums[DD / 4];          // 4 KB
    __shared__ float4 swp[NW][DD / 4];       // 32 KB warp-private partial S
    __shared__ float  red[3][NW];
    __shared__ float  wsum[NW];
    __shared__ float  sc_rdn;

    // ---- doc/summary: norms + doc·summary ----
    {
        const float4* docg = (const float4*)(doc  + (size_t)b * DD);
        const float4* sumg = (const float4*)(summ + (size_t)b * DD);
        float4 dv = docg[tid];
        float4 sv = sumg[tid];
        docs[tid] = dv;
        sums[tid] = sv;
        float pdd = dv.x*dv.x + dv.y*dv.y + dv.z*dv.z + dv.w*dv.w;
        float pss = sv.x*sv.x + sv.y*sv.y + sv.z*sv.z + sv.w*sv.w;
        float pds = dv.x*sv.x + dv.y*sv.y + dv.z*sv.z + dv.w*sv.w;
        #pragma unroll
        for (int o = 16; o; o >>= 1) {
            pdd += __shfl_xor_sync(0xffffffffu, pdd, o);
            pss += __shfl_xor_sync(0xffffffffu, pss, o);
            pds += __shfl_xor_sync(0xffffffffu, pds, o);
        }
        if (l == 0) { red[0][w] = pdd; red[1][w] = pss; red[2][w] = pds; }
    }
    __syncthreads();
    if (tid == 0) {
        float dd = 0.f, ss = 0.f, ds = 0.f;
        #pragma unroll
        for (int i = 0; i < NW; i++) { dd += red[0][i]; ss += red[1][i]; ds += red[2][i]; }
        float dn = fmaxf(sqrtf(dd), EPS);
        float sn = fmaxf(sqrtf(ss), EPS);
        sc_rdn = 1.0f / dn;
        if (half == 0) {
            out[2 * BB * CC + b] = ds / (dn * sn);      // summary_score[b]
            g_rsn[b] = 1.0f / sn;
        }
    }
    __syncthreads();
    const float rdn = sc_rdn;

    // ---- stream 64 rows: double-buffered 32B loads, evict_last pins in L2 ----
    const float* cb = cand + ((size_t)b * CC + row0) * DD;
    F8 Sacc[4];
    #pragma unroll
    for (int i = 0; i < 4; i++) {
        Sacc[i].lo = make_float4(0.f, 0.f, 0.f, 0.f);
        Sacc[i].hi = make_float4(0.f, 0.f, 0.f, 0.f);
    }
    float scpart = 0.f;

    F8 vc[4];
    {
        const float* rowp = cb + (size_t)w * DD;          // row w (j=0)
        #pragma unroll
        for (int i = 0; i < 4; i++) vc[i] = ldg_evict_last(rowp + (i * 32 + l) * 8);
    }

    #pragma unroll
    for (int j = 0; j < RPW; j++) {
        const int rl = w + j * NW;
        F8 vn[4];
        if (j + 1 < RPW) {
            const float* nrow = cb + (size_t)(rl + NW) * DD;
            #pragma unroll
            for (int i = 0; i < 4; i++) vn[i] = ldg_evict_last(nrow + (i * 32 + l) * 8);
        }

        // split accumulators on lo/hi: chains 16 deep
        float ss0 = 0.f, ss1 = 0.f, dd0 = 0.f, dd1 = 0.f, sd0 = 0.f, sd1 = 0.f;
        #pragma unroll
        for (int i = 0; i < 4; i++) {
            const int c = i * 32 + l;
            float4 a  = vc[i].lo;
            float4 d4 = docs[2 * c];
            float4 s4 = sums[2 * c];
            ss0 = fmaf(a.x, a.x, ss0); ss0 = fmaf(a.y, a.y, ss0);
            ss0 = fmaf(a.z, a.z, ss0); ss0 = fmaf(a.w, a.w, ss0);
            dd0 = fmaf(a.x, d4.x, dd0); dd0 = fmaf(a.y, d4.y, dd0);
            dd0 = fmaf(a.z, d4.z, dd0); dd0 = fmaf(a.w, d4.w, dd0);
            sd0 = fmaf(a.x, s4.x, sd0); sd0 = fmaf(a.y, s4.y, sd0);
            sd0 = fmaf(a.z, s4.z, sd0); sd0 = fmaf(a.w, s4.w, sd0);
            float4 a1  = vc[i].hi;
            float4 d41 = docs[2 * c + 1];
            float4 s41 = sums[2 * c + 1];
            ss1 = fmaf(a1.x, a1.x, ss1); ss1 = fmaf(a1.y, a1.y, ss1);
            ss1 = fmaf(a1.z, a1.z, ss1); ss1 = fmaf(a1.w, a1.w, ss1);
            dd1 = fmaf(a1.x, d41.x, dd1); dd1 = fmaf(a1.y, d41.y, dd1);
            dd1 = fmaf(a1.z, d41.z, dd1); dd1 = fmaf(a1.w, d41.w, dd1);
            sd1 = fmaf(a1.x, s41.x, sd1); sd1 = fmaf(a1.y, s41.y, sd1);
            sd1 = fmaf(a1.z, s41.z, sd1); sd1 = fmaf(a1.w, s41.w, sd1);
        }
        float ss = ss0 + ss1, dd = dd0 + dd1, sd = sd0 + sd1;
        #pragma unroll
        for (int o = 16; o; o >>= 1) {
            ss += __shfl_xor_sync(0xffffffffu, ss, o);
            dd += __shfl_xor_sync(0xffffffffu, dd, o);
            sd += __shfl_xor_sync(0xffffffffu, sd, o);
        }
        // rcn = 1/max(sqrt(ss), EPS) == rsqrt(max(ss, EPS^2))
        float rcn = rsqrtf(fmaxf(ss, EPS2));
        if (l == 0) {
            const int r = row0 + rl;
            out[b * CC + r] = dd * rcn * rdn;           // outer_score[b,r]
            g_rcn[b][r] = rcn;
        }
        scpart = fmaf(sd, rcn, scpart);                  // same across lanes
        #pragma unroll
        for (int i = 0; i < 4; i++) {
            Sacc[i].lo.x = fmaf(vc[i].lo.x, rcn, Sacc[i].lo.x);
            Sacc[i].lo.y = fmaf(vc[i].lo.y, rcn, Sacc[i].lo.y);
            Sacc[i].lo.z = fmaf(vc[i].lo.z, rcn, Sacc[i].lo.z);
            Sacc[i].lo.w = fmaf(vc[i].lo.w, rcn, Sacc[i].lo.w);
            Sacc[i].hi.x = fmaf(vc[i].hi.x, rcn, Sacc[i].hi.x);
            Sacc[i].hi.y = fmaf(vc[i].hi.y, rcn, Sacc[i].hi.y);
            Sacc[i].hi.z = fmaf(vc[i].hi.z, rcn, Sacc[i].hi.z);
            Sacc[i].hi.w = fmaf(vc[i].hi.w, rcn, Sacc[i].hi.w);
        }
        #pragma unroll
        for (int i = 0; i < 4; i++) vc[i] = vn[i];
    }

    // ---- fold warp partials; write half-batch S + scpart scratch ----
    #pragma unroll
    for (int i = 0; i < 4; i++) {
        const int c = i * 32 + l;
        swp[w][2 * c]     = Sacc[i].lo;
        swp[w][2 * c + 1] = Sacc[i].hi;
    }
    if (l == 0) wsum[w] = scpart;
    __syncthreads();
    {
        float4 st = swp[0][tid];
        #pragma unroll
        for (int ww = 1; ww < NW; ww++) {
            float4 t = swp[ww][tid];
            st.x += t.x; st.y += t.y; st.z += t.z; st.w += t.w;
        }
        ((float4*)g_Spart[b][half])[tid] = st;
    }
    if (tid == 0) {
        float acc = 0.f;
        #pragma unroll
        for (int i = 0; i < NW; i++) acc += wsum[i];
        g_scpart[b][half] = acc;
    }
}

// ====== K2: reverse-b stream (evict_first); inner scores ======
__global__ __launch_bounds__(256, 4) void k2_inner(
    const float* __restrict__ cand,
    float* __restrict__ out)
{
    const int b    = BB - 1 - (blockIdx.x >> 1);   // reversed: ride K1's L2-pinned tail
    const int half = blockIdx.x & 1;
    const int row0 = half * HALF_ROWS;
    const int tid  = threadIdx.x;
    const int w    = tid >> 5;
    const int l    = tid & 31;

    __shared__ float4 Ssm[DD / 4];   // 4 KB

    {
        const float4* s0 = (const float4*)g_Spart[b][0];
        const float4* s1 = (const float4*)g_Spart[b][1];
        float4 a = s0[tid];
        float4 c = s1[tid];
        a.x += c.x; a.y += c.y; a.z += c.z; a.w += c.w;
        Ssm[tid] = a;
    }
    if (half == 0 && tid == 0) {
        out[2 * BB * CC + BB + b] =
            (g_scpart[b][0] + g_scpart[b][1]) * g_rsn[b] * (1.0f / CC);  // summary_avg
    }
    __syncthreads();

    const float* cb = cand + ((size_t)b * CC + row0) * DD;

    F8 vc[4];
    {
        const float* rowp = cb + (size_t)w * DD;
        #pragma unroll
        for (int i = 0; i < 4; i++) vc[i] = ldg_evict_first(rowp + (i * 32 + l) * 8);
    }

    #pragma unroll
    for (int j = 0; j < RPW; j++) {
        const int rl = w + j * NW;
        F8 vn[4];
        if (j + 1 < RPW) {
            const float* nrow = cb + (size_t)(rl + NW) * DD;
            #pragma unroll
            for (int i = 0; i < 4; i++) vn[i] = ldg_evict_first(nrow + (i * 32 + l) * 8);
        }

        float dot0 = 0.f, dot1 = 0.f;
        #pragma unroll
        for (int i = 0; i < 4; i++) {
            const int c = i * 32 + l;
            float4 a = vc[i].lo;
            float4 s = Ssm[2 * c];
            dot0 = fmaf(a.x, s.x, dot0); dot0 = fmaf(a.y, s.y, dot0);
            dot0 = fmaf(a.z, s.z, dot0); dot0 = fmaf(a.w, s.w, dot0);
            float4 a1 = vc[i].hi;
            float4 s1 = Ssm[2 * c + 1];
            dot1 = fmaf(a1.x, s1.x, dot1); dot1 = fmaf(a1.y, s1.y, dot1);
            dot1 = fmaf(a1.z, s1.z, dot1); dot1 = fmaf(a1.w, s1.w, dot1);
        }
        float dot = dot0 + dot1;
        #pragma unroll
        for (int o = 16; o; o >>= 1)
            dot += __shfl_xor_sync(0xffffffffu, dot, o);
        if (l == 0) {
            const int r = row0 + rl;
            // chat_r · S includes the self term (==1 up to fp32 rounding)
            out[BB * CC + b * CC + r] =
                (dot * g_rcn[b][r] - 1.0f) * (1.0f / (CC - 1));
        }
        #pragma unroll
        for (int i = 0; i < 4; i++) vc[i] = vn[i];
    }
}

extern "C" void kernel_launch(void* const* d_in, const int* in_sizes, int n_in,
                              void* d_out, int out_size) {
    const float* doc  = (const float*)d_in[0];   // [B, D]
    const float* summ = (const float*)d_in[1];   // [B, D]
    const float* cand = (const float*)d_in[2];   // [B, C, D]
    float* out = (float*)d_out;                  // [B*C | B*C | B | B]
    (void)in_sizes; (void)n_in; (void)out_size;

    k1_stream<<<BB * 2, 256>>>(doc, summ, cand, out);
    k2_inner <<<BB * 2, 256>>>(cand, out);
}